// round 1
// baseline (speedup 1.0000x reference)
#include <cuda_runtime.h>
#include <math.h>

#define BATCH 32
#define CH    64
#define FM    128
#define HW    (FM*FM)          // 16384
#define CHW   (CH*HW)          // 1048576
#define TOTAL (BATCH*CHW)      // 33554432

// Scratch (allocation-free rule: __device__ globals)
__device__ float g_q[TOTAL];
__device__ float g_k[TOTAL];   // holds k + pos_code (folded)
__device__ float g_v[TOTAL];

// ---------------------------------------------------------------------------
// Kernel 1: QKV projection (1x1 conv = 64x64 channel mix), keff = k + pc
// Block: 64 out-ch x 256 pixels for one batch. Thread: 16 o x 4 p microtile.
// ---------------------------------------------------------------------------
__global__ __launch_bounds__(256) void qkv_kernel(
    const float* __restrict__ x,
    const float* __restrict__ wq, const float* __restrict__ bq,
    const float* __restrict__ wk, const float* __restrict__ bk,
    const float* __restrict__ wv, const float* __restrict__ bv,
    const float* __restrict__ pos)
{
    extern __shared__ float xs[];      // [64][256] input channels x pixels
    __shared__ float wsT[64 * 68];     // [c][o], pad 68 (bank-safe, 16B aligned rows)
    __shared__ float bsm[64];
    __shared__ float pcs[256];

    const int tid  = threadIdx.x;
    const int b    = blockIdx.y;
    const int pix0 = blockIdx.x * 256;
    const int to   = tid >> 6;   // 0..3   -> out channels to*16 .. to*16+15
    const int tp   = tid & 63;   // 0..63  -> pixels   tp*4  .. tp*4+3

    // load x tile (coalesced) and pos_code tile (channel 0 only: all channels equal)
    {
        const float* xp = x + (size_t)b * CHW + pix0 + tid;
        #pragma unroll
        for (int c = 0; c < 64; ++c)
            xs[c * 256 + tid] = xp[(size_t)c * HW];
    }
    pcs[tid] = pos[pix0 + tid];

    const float* W[3]  = {wq, wk, wv};
    const float* Bv[3] = {bq, bk, bv};
    float*       O[3]  = {g_q, g_k, g_v};

    for (int m = 0; m < 3; ++m) {
        __syncthreads();   // xs visible / previous compute done before wsT overwrite
        #pragma unroll
        for (int i = 0; i < 16; ++i) {
            int idx = i * 256 + tid;          // coalesced read of W
            int o = idx >> 6, c = idx & 63;
            wsT[c * 68 + o] = W[m][idx];
        }
        if (tid < 64) bsm[tid] = Bv[m][tid];
        __syncthreads();

        float acc[16][4];
        #pragma unroll
        for (int i = 0; i < 16; ++i)
            #pragma unroll
            for (int j = 0; j < 4; ++j) acc[i][j] = 0.f;

        #pragma unroll 4
        for (int c = 0; c < 64; ++c) {
            float xv[4];
            *(float4*)&xv[0] = *(const float4*)&xs[c * 256 + tp * 4];
            float w[16];
            const float4* wr = (const float4*)&wsT[c * 68 + to * 16];
            *(float4*)&w[0]  = wr[0];
            *(float4*)&w[4]  = wr[1];
            *(float4*)&w[8]  = wr[2];
            *(float4*)&w[12] = wr[3];
            #pragma unroll
            for (int i = 0; i < 16; ++i)
                #pragma unroll
                for (int j = 0; j < 4; ++j)
                    acc[i][j] += w[i] * xv[j];
        }

        float* outp = O[m] + (size_t)b * CHW;
        #pragma unroll
        for (int i = 0; i < 16; ++i) {
            int o = to * 16 + i;
            float bb = bsm[o];
            float4 r;
            r.x = acc[i][0] + bb;
            r.y = acc[i][1] + bb;
            r.z = acc[i][2] + bb;
            r.w = acc[i][3] + bb;
            if (m == 1) {  // keff = k + pos_code (same for every out channel)
                r.x += pcs[tp * 4 + 0];
                r.y += pcs[tp * 4 + 1];
                r.z += pcs[tp * 4 + 2];
                r.w += pcs[tp * 4 + 3];
            }
            *(float4*)&outp[(size_t)o * HW + pix0 + tp * 4] = r;
        }
    }
}

// ---------------------------------------------------------------------------
// Kernel 2: per-(b,c) attention: S = Q Keff^T (128x128x128), global softmax
// over all 16384 logits, out = softmax(S) * V elementwise.
// Q,K stored transposed in smem, row stride 132 (conflict-free float4 reads).
// ---------------------------------------------------------------------------
#define K2_LDS (132)
#define K2_SMEM (2 * 128 * K2_LDS * 4)

__global__ __launch_bounds__(256) void attn_kernel(float* __restrict__ out)
{
    extern __shared__ float sm[];
    float* Qt = sm;                    // [w][h], stride 132
    float* Kt = sm + 128 * K2_LDS;     // [w][v], stride 132
    __shared__ float redm[8];
    __shared__ float reds[8];

    const int tid = threadIdx.x;
    const size_t base = (size_t)blockIdx.x * HW;   // blockIdx.x = b*64 + c
    const int ty = tid >> 4;   // 0..15 -> rows ty*8..
    const int tx = tid & 15;   // 0..15 -> cols tx*8..

    const float* qg = g_q + base;
    const float* kg = g_k + base;
    #pragma unroll
    for (int i = 0; i < 64; ++i) {
        int idx = i * 256 + tid;       // coalesced global reads
        int h = idx >> 7, w = idx & 127;
        Qt[w * K2_LDS + h] = qg[idx];
        Kt[w * K2_LDS + h] = kg[idx];
    }
    __syncthreads();

    float acc[8][8];
    #pragma unroll
    for (int i = 0; i < 8; ++i)
        #pragma unroll
        for (int j = 0; j < 8; ++j) acc[i][j] = 0.f;

    #pragma unroll 2
    for (int kk = 0; kk < 128; ++kk) {
        float qv[8], kv[8];
        *(float4*)&qv[0] = *(const float4*)&Qt[kk * K2_LDS + ty * 8];
        *(float4*)&qv[4] = *(const float4*)&Qt[kk * K2_LDS + ty * 8 + 4];
        *(float4*)&kv[0] = *(const float4*)&Kt[kk * K2_LDS + tx * 8];
        *(float4*)&kv[4] = *(const float4*)&Kt[kk * K2_LDS + tx * 8 + 4];
        #pragma unroll
        for (int i = 0; i < 8; ++i)
            #pragma unroll
            for (int j = 0; j < 8; ++j)
                acc[i][j] += qv[i] * kv[j];
    }

    // ---- global max over all 16384 logits ----
    float mx = acc[0][0];
    #pragma unroll
    for (int i = 0; i < 8; ++i)
        #pragma unroll
        for (int j = 0; j < 8; ++j) mx = fmaxf(mx, acc[i][j]);
    #pragma unroll
    for (int off = 16; off; off >>= 1)
        mx = fmaxf(mx, __shfl_xor_sync(0xffffffffu, mx, off));
    if ((tid & 31) == 0) redm[tid >> 5] = mx;
    __syncthreads();
    float gm = redm[0];
    #pragma unroll
    for (int w = 1; w < 8; ++w) gm = fmaxf(gm, redm[w]);

    // ---- exp + global sum ----
    float s = 0.f;
    #pragma unroll
    for (int i = 0; i < 8; ++i)
        #pragma unroll
        for (int j = 0; j < 8; ++j) {
            acc[i][j] = __expf(acc[i][j] - gm);
            s += acc[i][j];
        }
    #pragma unroll
    for (int off = 16; off; off >>= 1)
        s += __shfl_xor_sync(0xffffffffu, s, off);
    if ((tid & 31) == 0) reds[tid >> 5] = s;
    __syncthreads();
    float gs = 0.f;
    #pragma unroll
    for (int w = 0; w < 8; ++w) gs += reds[w];
    const float inv = 1.0f / gs;

    // ---- out = att * v ----
    const float* vg = g_v + base;
    float* og = out + base;
    #pragma unroll
    for (int i = 0; i < 8; ++i) {
        int row = (ty * 8 + i) * 128 + tx * 8;
        float4 v0 = *(const float4*)&vg[row];
        float4 v1 = *(const float4*)&vg[row + 4];
        float4 o0, o1;
        o0.x = acc[i][0] * inv * v0.x;
        o0.y = acc[i][1] * inv * v0.y;
        o0.z = acc[i][2] * inv * v0.z;
        o0.w = acc[i][3] * inv * v0.w;
        o1.x = acc[i][4] * inv * v1.x;
        o1.y = acc[i][5] * inv * v1.y;
        o1.z = acc[i][6] * inv * v1.z;
        o1.w = acc[i][7] * inv * v1.w;
        *(float4*)&og[row]     = o0;
        *(float4*)&og[row + 4] = o1;
    }
}

// ---------------------------------------------------------------------------
extern "C" void kernel_launch(void* const* d_in, const int* in_sizes, int n_in,
                              void* d_out, int out_size)
{
    (void)in_sizes; (void)n_in; (void)out_size;
    const float* x  = (const float*)d_in[0];
    const float* wq = (const float*)d_in[1];
    const float* bq = (const float*)d_in[2];
    const float* wk = (const float*)d_in[3];
    const float* bk = (const float*)d_in[4];
    const float* wv = (const float*)d_in[5];
    const float* bv = (const float*)d_in[6];
    const float* pc = (const float*)d_in[7];
    float* out = (float*)d_out;

    cudaFuncSetAttribute(qkv_kernel, cudaFuncAttributeMaxDynamicSharedMemorySize, 65536);
    cudaFuncSetAttribute(attn_kernel, cudaFuncAttributeMaxDynamicSharedMemorySize, K2_SMEM);

    qkv_kernel<<<dim3(HW / 256, BATCH), 256, 65536>>>(x, wq, bq, wk, bk, wv, bv, pc);
    attn_kernel<<<BATCH * CH, 256, K2_SMEM>>>(out);
}